// round 7
// baseline (speedup 1.0000x reference)
#include <cuda_runtime.h>
#include <math.h>

#define B_CHAIN 16384
#define S_SIDE  15
#define NATM    (1 + B_CHAIN + B_CHAIN * S_SIDE)
#define P1_GRID (128 + 2048)

// 3x4 affine transform: rotation r[9] row-major, translation t[3]
struct M34 { float r[9]; float t[3]; };

__device__ __forceinline__ M34 m_identity() {
    M34 m;
    m.r[0]=1.f; m.r[1]=0.f; m.r[2]=0.f;
    m.r[3]=0.f; m.r[4]=1.f; m.r[5]=0.f;
    m.r[6]=0.f; m.r[7]=0.f; m.r[8]=1.f;
    m.t[0]=0.f; m.t[1]=0.f; m.t[2]=0.f;
    return m;
}

// C = A @ B  (A is the earlier transform)
__device__ __forceinline__ M34 compose(const M34& A, const M34& B) {
    M34 C;
#pragma unroll
    for (int i = 0; i < 3; i++) {
#pragma unroll
        for (int j = 0; j < 3; j++) {
            C.r[i*3+j] = fmaf(A.r[i*3+0], B.r[0*3+j],
                          fmaf(A.r[i*3+1], B.r[1*3+j],
                               A.r[i*3+2] * B.r[2*3+j]));
        }
        C.t[i] = fmaf(A.r[i*3+0], B.t[0],
                  fmaf(A.r[i*3+1], B.t[1],
                   fmaf(A.r[i*3+2], B.t[2], A.t[i])));
    }
    return C;
}

__device__ __forceinline__ M34 shflup(const M34& v, int d, int width) {
    M34 o;
#pragma unroll
    for (int k = 0; k < 9; k++) o.r[k] = __shfl_up_sync(0xffffffffu, v.r[k], d, width);
#pragma unroll
    for (int k = 0; k < 3; k++) o.t[k] = __shfl_up_sync(0xffffffffu, v.t[k], d, width);
    return o;
}

// FMA-pipe sincos: magic-number quadrant reduction + cephes minimax polys on
// [-pi/4, pi/4]. Valid for |x| << 2^22 (here |x| < 3). Max err ~1.2e-7.
__device__ __forceinline__ void poly_sincos(float x, float* sp, float* cp) {
    const float MAGIC = 12582912.0f;             // 1.5 * 2^23
    float k = fmaf(x, 0.63661977236758134f, MAGIC);
    int   q = __float_as_int(k);
    float n = k - MAGIC;
    float r = fmaf(n, -1.57079637e+00f, x);      // pi/2 hi
    r       = fmaf(n,  4.37113883e-08f, r);      // pi/2 lo correction
    float z = r * r;
    float ps = fmaf(z, fmaf(z, -1.9515295891e-4f, 8.3321608736e-3f), -1.6666654611e-1f);
    ps = fmaf(ps * z, r, r);
    float pc = fmaf(z, fmaf(z, 2.44331571e-5f, -1.38873163e-3f), 4.16666457e-2f);
    pc = fmaf(pc, z * z, fmaf(-0.5f, z, 1.0f));
    bool swap = (q & 1);
    float s = swap ? pc : ps;
    float c = swap ? ps : pc;
    if (q & 2) s = -s;
    if ((q + 1) & 2) c = -c;
    *sp = s; *cp = c;
}

// Bond matrix: Rx(a)*Rz(b)*T(c,0,0)*Rx(d) given sin/cos of the three angles.
__device__ __forceinline__ M34 bond_mat(float sa, float ca, float sb, float cb,
                                        float sd, float cd, float c) {
    M34 m;
    m.r[0] = cb;      m.r[1] = -cd * sb;                 m.r[2] = sd * sb;
    m.r[3] = ca * sb; m.r[4] = fmaf(cd*ca, cb, -sd*sa);  m.r[5] = fmaf(-sd*ca, cb, -cd*sa);
    m.r[6] = sa * sb; m.r[7] = fmaf(cd*sa, cb,  sd*ca);  m.r[8] = fmaf(-sd*sa, cb,  cd*ca);
    m.t[0] = c * cb;
    m.t[1] = c * ca * sb;
    m.t[2] = c * sa * sb;
    return m;
}

// Accurate build (backbone — error accumulates over 16k composes)
__device__ __forceinline__ M34 build_ht_acc(int n,
                                            const float* __restrict__ dofs,
                                            const float* __restrict__ full_dofs,
                                            int dt) {
    if (dt == 2) {
        float4 dv = *(const float4*)(dofs + 4 * (n - 1));
        float sa, ca, sb, cb, sd, cd;
        sincosf(dv.x, &sa, &ca);
        sincosf(dv.y, &sb, &cb);
        sincosf(dv.w, &sd, &cd);
        return bond_mat(sa, ca, sb, cb, sd, cd, dv.z);
    } else if (dt == 1) {
        float4 dv = *(const float4*)(dofs + 4 * (n - 1));
        float f = full_dofs[9 * n + 4];
        float e = full_dofs[9 * n + 5];
        float sd, cd, sf, cf, se, ce;
        sincosf(dv.w, &sd, &cd);
        sincosf(f, &sf, &cf);
        sincosf(e, &se, &ce);
        M34 m;
        m.r[0] = ce * cf;  m.r[1] = fmaf(sd*ce, sf, -cd*se);  m.r[2] = fmaf(cd*ce, sf,  sd*se);
        m.r[3] = se * cf;  m.r[4] = fmaf(sd*se, sf,  cd*ce);  m.r[5] = fmaf(cd*se, sf, -sd*ce);
        m.r[6] = -sf;      m.r[7] = sd * cf;                  m.r[8] = cd * cf;
        m.t[0] = dv.x; m.t[1] = dv.y; m.t[2] = dv.z;
        return m;
    }
    return m_identity();
}

// Fast build (side chains — depth <= 15, FMA-pipe poly sincos)
__device__ __forceinline__ M34 build_ht_fast(int n,
                                             const float* __restrict__ dofs,
                                             const float* __restrict__ full_dofs,
                                             int dt) {
    if (dt == 2) {
        float4 dv = *(const float4*)(dofs + 4 * (n - 1));
        float sa, ca, sb, cb, sd, cd;
        poly_sincos(dv.x, &sa, &ca);
        poly_sincos(dv.y, &sb, &cb);
        poly_sincos(dv.w, &sd, &cd);
        return bond_mat(sa, ca, sb, cb, sd, cd, dv.z);
    } else if (dt == 1) {
        float4 dv = *(const float4*)(dofs + 4 * (n - 1));
        float f = full_dofs[9 * n + 4];
        float e = full_dofs[9 * n + 5];
        float sd, cd, sf, cf, se, ce;
        poly_sincos(dv.w, &sd, &cd);
        poly_sincos(f, &sf, &cf);
        poly_sincos(e, &se, &ce);
        M34 m;
        m.r[0] = ce * cf;  m.r[1] = fmaf(sd*ce, sf, -cd*se);  m.r[2] = fmaf(cd*ce, sf,  sd*se);
        m.r[3] = se * cf;  m.r[4] = fmaf(sd*se, sf,  cd*ce);  m.r[5] = fmaf(cd*se, sf, -sd*ce);
        m.r[6] = -sf;      m.r[7] = sd * cf;                  m.r[8] = cd * cf;
        m.t[0] = dv.x; m.t[1] = dv.y; m.t[2] = dv.z;
        return m;
    }
    return m_identity();
}

// Scratch (allocation-free: __device__ globals)
__device__ float g_L[12][B_CHAIN];          // backbone block-local inclusive products (SoA)
__device__ float g_Agg[128][12];            // per-block aggregates
__device__ float g_P[128][12];              // exclusive chunk prefixes
__device__ float g_St[B_CHAIN][48];         // side-chain inclusive translations (AoS, 45 used)
__device__ unsigned int g_done;             // phase1 completion counter (self-resetting)

// Inclusive Kogge-Stone scan across 128 threads (4 warps)
__device__ __forceinline__ void block_scan_128(M34& v, int tid, M34* sAgg) {
    int lane = tid & 31, w = tid >> 5;
#pragma unroll
    for (int d = 1; d < 32; d <<= 1) {
        M34 o = shflup(v, d, 32);
        if (lane >= d) v = compose(o, v);
    }
    if (lane == 31) sAgg[w] = v;
    __syncthreads();
    if (w > 0) {
        M34 p = sAgg[0];
        for (int k = 1; k < w; k++) p = compose(p, sAgg[k]);
        v = compose(p, v);
    }
}

// Phase 1:
//   blocks [0,128):        backbone block-local scans (accurate sincos)
//   blocks [128,128+2048): side chains, 16 lanes/chain (poly sincos + seg. scan)
//   LAST block to finish:  scans the 128 aggregates -> g_P (fused phase 2)
__global__ void __launch_bounds__(128)
k_phase1(const float* __restrict__ dofs,
         const float* __restrict__ full_dofs,
         const int* __restrict__ doftype) {
    __shared__ M34 sAgg[4];
    __shared__ bool sLast;
    int blk = blockIdx.x;
    int tid = threadIdx.x;

    if (blk < 128) {
        int t = blk * 128 + tid;       // 0..16383
        int n = t + 1;                 // backbone node 1..16384
        int dt = doftype[n];
        M34 v = build_ht_acc(n, dofs, full_dofs, dt);
        block_scan_128(v, tid, sAgg);
#pragma unroll
        for (int c = 0; c < 9; c++) g_L[c][t] = v.r[c];
#pragma unroll
        for (int c = 0; c < 3; c++) g_L[9 + c][t] = v.t[c];
        if (tid == 127) {
#pragma unroll
            for (int c = 0; c < 9; c++) g_Agg[blk][c] = v.r[c];
#pragma unroll
            for (int c = 0; c < 3; c++) g_Agg[blk][9 + c] = v.t[c];
        }
    } else {
        int sblk   = blk - 128;            // 0..2047
        int group  = tid >> 4;             // 0..7
        int lane16 = tid & 15;             // atom-in-chain (15 real + 1 pad)
        int chain  = sblk * 8 + group;     // 0..16383

        M34 v;
        if (lane16 < S_SIDE) {
            int ns = 1 + B_CHAIN + chain * S_SIDE + lane16;
            int dt = doftype[ns];
            v = build_ht_fast(ns, dofs, full_dofs, dt);
        } else {
            v = m_identity();
        }
#pragma unroll
        for (int d = 1; d < 16; d <<= 1) {
            M34 o = shflup(v, d, 16);
            if (lane16 >= d) v = compose(o, v);
        }
        if (lane16 < S_SIDE) {
            float* st = &g_St[chain][lane16 * 3];
            st[0] = v.t[0];
            st[1] = v.t[1];
            st[2] = v.t[2];
        }
    }

    // ---- last-block-done: fused aggregate scan (phase 2) ----
    __syncthreads();
    if (tid == 0) {
        __threadfence();
        unsigned int prev = atomicAdd(&g_done, 1u);
        sLast = (prev == (unsigned int)(P1_GRID - 1));
    }
    __syncthreads();
    if (sLast) {
        M34 a;
#pragma unroll
        for (int c = 0; c < 9; c++) a.r[c] = g_Agg[tid][c];
#pragma unroll
        for (int c = 0; c < 3; c++) a.t[c] = g_Agg[tid][9 + c];
        block_scan_128(a, tid, sAgg);
        if (tid == 0) {
            M34 I = m_identity();
#pragma unroll
            for (int c = 0; c < 9; c++) g_P[0][c] = I.r[c];
#pragma unroll
            for (int c = 0; c < 3; c++) g_P[0][9 + c] = I.t[c];
        }
        if (tid < 127) {
#pragma unroll
            for (int c = 0; c < 9; c++) g_P[tid + 1][c] = a.r[c];
#pragma unroll
            for (int c = 0; c < 3; c++) g_P[tid + 1][9 + c] = a.t[c];
        }
        __syncthreads();
        if (tid == 0) g_done = 0;  // self-reset for graph replay
    }
}

// Apply: 2048 blocks; chunk prefix read directly from g_P. 16 lanes per
// backbone node: lane 15 writes backbone coord, lanes 0..14 matvec one side atom.
__global__ void __launch_bounds__(128)
k_apply(const int* __restrict__ kin_id, float* __restrict__ out) {
    int blk = blockIdx.x, tid = threadIdx.x;
    int chunk = blk >> 4;

    M34 P;
#pragma unroll
    for (int c = 0; c < 9; c++) P.r[c] = g_P[chunk][c];
#pragma unroll
    for (int c = 0; c < 3; c++) P.t[c] = g_P[chunk][9 + c];

    int group  = tid >> 4;
    int lane16 = tid & 15;
    int t = blk * 8 + group;   // backbone index 0..16383

    M34 L;
#pragma unroll
    for (int c = 0; c < 9; c++) L.r[c] = g_L[c][t];
#pragma unroll
    for (int c = 0; c < 3; c++) L.t[c] = g_L[9 + c][t];

    M34 G = compose(P, L);

    if (lane16 == 15) {
        int kid = kin_id[t + 1];
        out[3 * kid + 0] = G.t[0];
        out[3 * kid + 1] = G.t[1];
        out[3 * kid + 2] = G.t[2];
    } else {
        const float* st = &g_St[t][lane16 * 3];
        float x = st[0], y = st[1], z = st[2];
        float vx = fmaf(G.r[0], x, fmaf(G.r[1], y, fmaf(G.r[2], z, G.t[0])));
        float vy = fmaf(G.r[3], x, fmaf(G.r[4], y, fmaf(G.r[5], z, G.t[1])));
        float vz = fmaf(G.r[6], x, fmaf(G.r[7], y, fmaf(G.r[8], z, G.t[2])));
        int ns = 1 + B_CHAIN + t * S_SIDE + lane16;
        int k2 = kin_id[ns];
        out[3 * k2 + 0] = vx;
        out[3 * k2 + 1] = vy;
        out[3 * k2 + 2] = vz;
    }
}

extern "C" void kernel_launch(void* const* d_in, const int* in_sizes, int n_in,
                              void* d_out, int out_size) {
    const float* dofs      = (const float*)d_in[0];
    const float* full_dofs = (const float*)d_in[1];
    const int*   doftype   = (const int*)d_in[4];
    const int*   kin_id    = (const int*)d_in[8];
    float* out = (float*)d_out;

    k_phase1<<<P1_GRID, 128>>>(dofs, full_dofs, doftype);
    k_apply<<<2048, 128>>>(kin_id, out);
}

// round 8
// speedup vs baseline: 1.1214x; 1.1214x over previous
#include <cuda_runtime.h>
#include <math.h>

#define B_CHAIN 16384
#define S_SIDE  15
#define NATM    (1 + B_CHAIN + B_CHAIN * S_SIDE)
#define NBLK_BB 128
#define NBLK_SC 512
#define NBLK    (NBLK_BB + NBLK_SC)

// 3x4 affine transform: rotation r[9] row-major, translation t[3]
struct M34 { float r[9]; float t[3]; };

__device__ __forceinline__ M34 m_identity() {
    M34 m;
    m.r[0]=1.f; m.r[1]=0.f; m.r[2]=0.f;
    m.r[3]=0.f; m.r[4]=1.f; m.r[5]=0.f;
    m.r[6]=0.f; m.r[7]=0.f; m.r[8]=1.f;
    m.t[0]=0.f; m.t[1]=0.f; m.t[2]=0.f;
    return m;
}

// C = A @ B  (A is the earlier transform)
__device__ __forceinline__ M34 compose(const M34& A, const M34& B) {
    M34 C;
#pragma unroll
    for (int i = 0; i < 3; i++) {
#pragma unroll
        for (int j = 0; j < 3; j++) {
            C.r[i*3+j] = fmaf(A.r[i*3+0], B.r[0*3+j],
                          fmaf(A.r[i*3+1], B.r[1*3+j],
                               A.r[i*3+2] * B.r[2*3+j]));
        }
        C.t[i] = fmaf(A.r[i*3+0], B.t[0],
                  fmaf(A.r[i*3+1], B.t[1],
                   fmaf(A.r[i*3+2], B.t[2], A.t[i])));
    }
    return C;
}

__device__ __forceinline__ M34 shflup(const M34& v, int d, int width) {
    M34 o;
#pragma unroll
    for (int k = 0; k < 9; k++) o.r[k] = __shfl_up_sync(0xffffffffu, v.r[k], d, width);
#pragma unroll
    for (int k = 0; k < 3; k++) o.t[k] = __shfl_up_sync(0xffffffffu, v.t[k], d, width);
    return o;
}

// FMA-pipe sincos: magic-number quadrant reduction + cephes minimax polys.
// Valid for |x| << 2^22 (here |x| < 3). Max err ~1.2e-7.
__device__ __forceinline__ void poly_sincos(float x, float* sp, float* cp) {
    const float MAGIC = 12582912.0f;             // 1.5 * 2^23
    float k = fmaf(x, 0.63661977236758134f, MAGIC);
    int   q = __float_as_int(k);
    float n = k - MAGIC;
    float r = fmaf(n, -1.57079637e+00f, x);      // pi/2 hi
    r       = fmaf(n,  4.37113883e-08f, r);      // pi/2 lo correction
    float z = r * r;
    float ps = fmaf(z, fmaf(z, -1.9515295891e-4f, 8.3321608736e-3f), -1.6666654611e-1f);
    ps = fmaf(ps * z, r, r);
    float pc = fmaf(z, fmaf(z, 2.44331571e-5f, -1.38873163e-3f), 4.16666457e-2f);
    pc = fmaf(pc, z * z, fmaf(-0.5f, z, 1.0f));
    bool swap = (q & 1);
    float s = swap ? pc : ps;
    float c = swap ? ps : pc;
    if (q & 2) s = -s;
    if ((q + 1) & 2) c = -c;
    *sp = s; *cp = c;
}

// Bond matrix: Rx(a)*Rz(b)*T(c,0,0)*Rx(d) given sin/cos of the three angles.
__device__ __forceinline__ M34 bond_mat(float sa, float ca, float sb, float cb,
                                        float sd, float cd, float c) {
    M34 m;
    m.r[0] = cb;      m.r[1] = -cd * sb;                 m.r[2] = sd * sb;
    m.r[3] = ca * sb; m.r[4] = fmaf(cd*ca, cb, -sd*sa);  m.r[5] = fmaf(-sd*ca, cb, -cd*sa);
    m.r[6] = sa * sb; m.r[7] = fmaf(cd*sa, cb,  sd*ca);  m.r[8] = fmaf(-sd*sa, cb,  cd*ca);
    m.t[0] = c * cb;
    m.t[1] = c * ca * sb;
    m.t[2] = c * sa * sb;
    return m;
}

// Accurate build (backbone — error accumulates over 16k composes)
__device__ __forceinline__ M34 build_ht_acc(int n,
                                            const float* __restrict__ dofs,
                                            const float* __restrict__ full_dofs,
                                            int dt) {
    if (dt == 2) {
        float4 dv = *(const float4*)(dofs + 4 * (n - 1));
        float sa, ca, sb, cb, sd, cd;
        sincosf(dv.x, &sa, &ca);
        sincosf(dv.y, &sb, &cb);
        sincosf(dv.w, &sd, &cd);
        return bond_mat(sa, ca, sb, cb, sd, cd, dv.z);
    } else if (dt == 1) {
        float4 dv = *(const float4*)(dofs + 4 * (n - 1));
        float f = full_dofs[9 * n + 4];
        float e = full_dofs[9 * n + 5];
        float sd, cd, sf, cf, se, ce;
        sincosf(dv.w, &sd, &cd);
        sincosf(f, &sf, &cf);
        sincosf(e, &se, &ce);
        M34 m;
        m.r[0] = ce * cf;  m.r[1] = fmaf(sd*ce, sf, -cd*se);  m.r[2] = fmaf(cd*ce, sf,  sd*se);
        m.r[3] = se * cf;  m.r[4] = fmaf(sd*se, sf,  cd*ce);  m.r[5] = fmaf(cd*se, sf, -sd*ce);
        m.r[6] = -sf;      m.r[7] = sd * cf;                  m.r[8] = cd * cf;
        m.t[0] = dv.x; m.t[1] = dv.y; m.t[2] = dv.z;
        return m;
    }
    return m_identity();
}

// Fast bond build (side chains are all doftype==2 by construction)
__device__ __forceinline__ M34 build_bond_fast(int n, const float* __restrict__ dofs) {
    float4 dv = *(const float4*)(dofs + 4 * (n - 1));
    float sa, ca, sb, cb, sd, cd;
    poly_sincos(dv.x, &sa, &ca);
    poly_sincos(dv.y, &sb, &cb);
    poly_sincos(dv.w, &sd, &cd);
    return bond_mat(sa, ca, sb, cb, sd, cd, dv.z);
}

// Scratch (allocation-free: __device__ globals)
__device__ float g_L[12][B_CHAIN];   // backbone block-local inclusive products (SoA)
__device__ float g_Agg[128][12];     // per-backbone-block aggregates
__device__ float g_P[128][12];       // exclusive chunk prefixes
__device__ unsigned int g_cnt_bb;    // backbone blocks completed (self-reset)
__device__ unsigned int g_cnt_all;   // all blocks completed (self-reset)
__device__ int g_flag;               // g_P-ready flag (self-reset)

__device__ __forceinline__ int ld_acquire(int* p) {
    int v;
    asm volatile("ld.acquire.gpu.global.b32 %0, [%1];" : "=r"(v) : "l"(p) : "memory");
    return v;
}
__device__ __forceinline__ void st_release(int* p, int v) {
    asm volatile("st.release.gpu.global.b32 [%0], %1;" :: "l"(p), "r"(v) : "memory");
}

// Inclusive Kogge-Stone scan across 128 threads (4 warps)
__device__ __forceinline__ void block_scan_128(M34& v, int tid, M34* sAgg) {
    int lane = tid & 31, w = tid >> 5;
#pragma unroll
    for (int d = 1; d < 32; d <<= 1) {
        M34 o = shflup(v, d, 32);
        if (lane >= d) v = compose(o, v);
    }
    if (lane == 31) sAgg[w] = v;
    __syncthreads();
    if (w > 0) {
        M34 p = sAgg[0];
        for (int k = 1; k < w; k++) p = compose(p, sAgg[k]);
        v = compose(p, v);
    }
}

__device__ __forceinline__ void load_P(int row, M34& P) {
#pragma unroll
    for (int c = 0; c < 9; c++) P.r[c] = __ldcg(&g_P[row][c]);
#pragma unroll
    for (int c = 0; c < 3; c++) P.t[c] = __ldcg(&g_P[row][9 + c]);
}

// Single fused kernel. All NBLK blocks are co-resident (launch_bounds
// guarantees >=6 blocks/SM -> capacity 888 >= 640), so the spin barrier
// cannot deadlock.
__global__ void __launch_bounds__(128, 6)
k_fused(const float* __restrict__ dofs,
        const float* __restrict__ full_dofs,
        const int* __restrict__ doftype,
        const int* __restrict__ kin_id,
        float* __restrict__ out) {
    __shared__ M34 sAgg[4];
    __shared__ bool sLast;
    int blk = blockIdx.x;
    int tid = threadIdx.x;

    if (blk < NBLK_BB) {
        // ---------------- backbone ----------------
        int t = blk * 128 + tid;       // 0..16383
        int n = t + 1;                 // backbone node
        int kid = kin_id[n];           // prefetch
        int dt = doftype[n];
        M34 v = build_ht_acc(n, dofs, full_dofs, dt);
        block_scan_128(v, tid, sAgg);
#pragma unroll
        for (int c = 0; c < 9; c++) g_L[c][t] = v.r[c];
#pragma unroll
        for (int c = 0; c < 3; c++) g_L[9 + c][t] = v.t[c];
        if (tid == 127) {
#pragma unroll
            for (int c = 0; c < 9; c++) g_Agg[blk][c] = v.r[c];
#pragma unroll
            for (int c = 0; c < 3; c++) g_Agg[blk][9 + c] = v.t[c];
        }
        __threadfence();
        __syncthreads();
        if (tid == 0) {
            unsigned int prev = atomicAdd(&g_cnt_bb, 1u);
            sLast = (prev == NBLK_BB - 1);
        }
        __syncthreads();
        if (sLast) {
            // 128th backbone block: scan aggregates -> g_P, publish flag
            M34 a;
#pragma unroll
            for (int c = 0; c < 9; c++) a.r[c] = g_Agg[tid][c];
#pragma unroll
            for (int c = 0; c < 3; c++) a.t[c] = g_Agg[tid][9 + c];
            block_scan_128(a, tid, sAgg);
            if (tid == 0) {
                M34 I = m_identity();
#pragma unroll
                for (int c = 0; c < 9; c++) g_P[0][c] = I.r[c];
#pragma unroll
                for (int c = 0; c < 3; c++) g_P[0][9 + c] = I.t[c];
            }
            if (tid < 127) {
#pragma unroll
                for (int c = 0; c < 9; c++) g_P[tid + 1][c] = a.r[c];
#pragma unroll
                for (int c = 0; c < 3; c++) g_P[tid + 1][9 + c] = a.t[c];
            }
            __threadfence();
            __syncthreads();
            if (tid == 0) {
                g_cnt_bb = 0;            // self-reset for graph replay
                st_release(&g_flag, 1);
            }
            __syncthreads();
        } else {
            if (tid == 0) {
                while (ld_acquire(&g_flag) == 0) __nanosleep(64);
            }
            __syncthreads();
        }
        // apply own prefix, write backbone coord (L still in regs as v)
        M34 P;
        load_P(blk, P);
        M34 G = compose(P, v);
        out[3 * kid + 0] = G.t[0];
        out[3 * kid + 1] = G.t[1];
        out[3 * kid + 2] = G.t[2];
    } else {
        // ---------------- side chains: 4 lanes per chain ----------------
        int sblk  = blk - NBLK_BB;         // 0..511
        int lane4 = tid & 3;
        int chain = sblk * 32 + (tid >> 2);  // 0..16383
        int base  = lane4 * 4;               // first atom-in-chain for this lane
        int cnt   = (lane4 == 3) ? 3 : 4;
        int a0    = 1 + B_CHAIN + chain * S_SIDE + base;  // global atom index

        // prefetch scatter ids
        int kid[4];
#pragma unroll
        for (int i = 0; i < 4; i++)
            kid[i] = (i < cnt) ? kin_id[a0 + i] : 0;

        // serial build of this lane's 3-4 atoms, recording running translations
        float tr[4][3];
        M34 run = build_bond_fast(a0, dofs);
        tr[0][0] = run.t[0]; tr[0][1] = run.t[1]; tr[0][2] = run.t[2];
#pragma unroll
        for (int i = 1; i < 4; i++) {
            if (i < cnt) {
                M34 h = build_bond_fast(a0 + i, dofs);
                run = compose(run, h);
                tr[i][0] = run.t[0]; tr[i][1] = run.t[1]; tr[i][2] = run.t[2];
            }
        }

        // inclusive scan over the 4 lanes of this chain
#pragma unroll
        for (int d = 1; d < 4; d <<= 1) {
            M34 o = shflup(run, d, 4);
            if (lane4 >= d) run = compose(o, run);
        }
        // exclusive prefix: lane j gets lane j-1's inclusive (lane0 -> identity)
        M34 E = shflup(run, 1, 4);

        // wait for backbone global prefixes
        if (tid == 0) {
            while (ld_acquire(&g_flag) == 0) __nanosleep(64);
        }
        __syncthreads();

        // parent global transform: G = g_P[chain>>7] @ g_L[chain]
        M34 P, L;
        load_P(chain >> 7, P);
#pragma unroll
        for (int c = 0; c < 9; c++) L.r[c] = __ldcg(&g_L[c][chain]);
#pragma unroll
        for (int c = 0; c < 3; c++) L.t[c] = __ldcg(&g_L[9 + c][chain]);
        M34 Gp = compose(P, L);
        M34 F = (lane4 == 0) ? Gp : compose(Gp, E);

#pragma unroll
        for (int i = 0; i < 4; i++) {
            if (i < cnt) {
                float x = tr[i][0], y = tr[i][1], z = tr[i][2];
                float vx = fmaf(F.r[0], x, fmaf(F.r[1], y, fmaf(F.r[2], z, F.t[0])));
                float vy = fmaf(F.r[3], x, fmaf(F.r[4], y, fmaf(F.r[5], z, F.t[1])));
                float vz = fmaf(F.r[6], x, fmaf(F.r[7], y, fmaf(F.r[8], z, F.t[2])));
                out[3 * kid[i] + 0] = vx;
                out[3 * kid[i] + 1] = vy;
                out[3 * kid[i] + 2] = vz;
            }
        }
    }

    // ---- final reset of the flag for graph replay ----
    if (tid == 0) {
        unsigned int prev = atomicAdd(&g_cnt_all, 1u);
        if (prev == NBLK - 1) {
            g_cnt_all = 0;
            g_flag = 0;
        }
    }
}

extern "C" void kernel_launch(void* const* d_in, const int* in_sizes, int n_in,
                              void* d_out, int out_size) {
    const float* dofs      = (const float*)d_in[0];
    const float* full_dofs = (const float*)d_in[1];
    const int*   doftype   = (const int*)d_in[4];
    const int*   kin_id    = (const int*)d_in[8];
    float* out = (float*)d_out;

    k_fused<<<NBLK, 128>>>(dofs, full_dofs, doftype, kin_id, out);
}